// round 10
// baseline (speedup 1.0000x reference)
#include <cuda_runtime.h>
#include <cuda_bf16.h>
#include <math.h>

#define Nn   50000
#define Ee   800000
#define ENb  (Ee + Nn)
#define Cc   128
#define Hh   4
#define Gg   512
#define OUTC 100
#define NEG  0.2f
#define EPSf 1e-16f

typedef unsigned long long ull;

#define PACK2(out, lo, hi) \
    asm("mov.b64 %0, {%1, %2};" : "=l"(out) : "r"(__float_as_uint(lo)), "r"(__float_as_uint(hi)))
#define UNPACK2(lo, hi, in) \
    do { unsigned _ul, _uh; \
         asm("mov.b64 {%0, %1}, %2;" : "=r"(_ul), "=r"(_uh) : "l"(in)); \
         lo = __uint_as_float(_ul); hi = __uint_as_float(_uh); } while (0)
#define FMA2(d, a, b) \
    asm("fma.rn.f32x2 %0, %1, %2, %0;" : "+l"(d) : "l"(a), "l"(b))

// ---- scratch (device globals: no allocations allowed) ----
__device__ __align__(16) float g_feat[Nn * Cc];           // layer output / next input (fp32)
__device__ __align__(16) __nv_bfloat16 g_hb[Nn * Cc];     // transformed features, bf16 (agg-only)
__device__ __align__(16) float g_asrc[Nn * Hh];
__device__ __align__(16) float g_adst[Nn * Hh];
__device__ int   g_rowptr[Nn + 1];
__device__ int   g_cursor[Nn];
__device__ int   g_col[ENb];
__device__ __align__(16) float g_sums[Gg * Cc];
__device__ float g_cnt[Gg];

// ---------------- init: deg=1 (self loop), zero pool accumulators ----------------
__global__ void k_init() {
    int i = blockIdx.x * 256 + threadIdx.x;
    if (i < Gg * Cc) g_sums[i] = 0.f;
    if (i < Gg)      g_cnt[i]  = 0.f;
    if (i < Nn)      g_cursor[i] = 1;   // self loop counted
}

// ---------------- histogram over dst, 4 edges/thread ----------------
__global__ void k_hist(const int* __restrict__ ei) {
    int idx = blockIdx.x * 256 + threadIdx.x;
    if (idx >= Ee / 4) return;
    int4 d = *(const int4*)&ei[Ee + idx * 4];
    atomicAdd(&g_cursor[d.x], 1);
    atomicAdd(&g_cursor[d.y], 1);
    atomicAdd(&g_cursor[d.z], 1);
    atomicAdd(&g_cursor[d.w], 1);
}

// ---------------- single-block exclusive scan (N=50000) ----------------
__global__ void k_scan() {
    __shared__ int s[1024];
    int t = threadIdx.x;
    const int PER = (Nn + 1023) / 1024;   // 49
    int base = t * PER;
    int sum = 0;
    for (int i = 0; i < PER; i++) {
        int idx = base + i;
        if (idx < Nn) sum += g_cursor[idx];
    }
    s[t] = sum;
    __syncthreads();
    for (int o = 1; o < 1024; o <<= 1) {
        int u = (t >= o) ? s[t - o] : 0;
        __syncthreads();
        s[t] += u;
        __syncthreads();
    }
    int off = s[t] - sum;                 // exclusive prefix
    for (int i = 0; i < PER; i++) {
        int idx = base + i;
        if (idx < Nn) {
            int d = g_cursor[idx];
            g_rowptr[idx] = off;
            g_cursor[idx] = off;          // scatter cursor
            off += d;
        }
    }
    if (t == 1023) g_rowptr[Nn] = s[1023];
}

// ---------------- scatter edges + self loops into CSR, 4/thread ----------------
__global__ void k_scatter(const int* __restrict__ ei) {
    int idx = blockIdx.x * 256 + threadIdx.x;
    const int EQ = Ee / 4;                 // 200000
    const int NQ = Nn / 4;                 // 12500
    if (idx < EQ) {
        int4 d = *(const int4*)&ei[Ee + idx * 4];
        int4 s = *(const int4*)&ei[idx * 4];
        int p0 = atomicAdd(&g_cursor[d.x], 1);
        int p1 = atomicAdd(&g_cursor[d.y], 1);
        int p2 = atomicAdd(&g_cursor[d.z], 1);
        int p3 = atomicAdd(&g_cursor[d.w], 1);
        g_col[p0] = s.x;
        g_col[p1] = s.y;
        g_col[p2] = s.z;
        g_col[p3] = s.w;
    } else if (idx < EQ + NQ) {
        int n = (idx - EQ) * 4;
        int p0 = atomicAdd(&g_cursor[n + 0], 1);
        int p1 = atomicAdd(&g_cursor[n + 1], 1);
        int p2 = atomicAdd(&g_cursor[n + 2], 1);
        int p3 = atomicAdd(&g_cursor[n + 3], 1);
        g_col[p0] = n + 0;
        g_col[p1] = n + 1;
        g_col[p2] = n + 2;
        g_col[p3] = n + 3;
    }
}

// ---------------- fused GEMM (f32x2, double-buffered) + attention logits ----------------
// g_hb[N,128](bf16) = X[N,128] @ W[128,128]^T, plus per-head att dots (fp32).
// BM=128, BN=64, BK=16, 256 threads, 8x4 per thread, f32x2 row-pair accumulators.
template<bool FROM_GLOBAL>
__global__ __launch_bounds__(256) void k_gemm(const float* __restrict__ X,
                                              const float* __restrict__ W,
                                              const float* __restrict__ AS,
                                              const float* __restrict__ AD) {
    __shared__ __align__(16) float ftT[2][16][132];   // [buf][k][row]
    __shared__ __align__(16) float wtT[2][16][68];    // [buf][k][col]
    const float* __restrict__ src = FROM_GLOBAL ? (const float*)g_feat : X;
    int t = threadIdx.x;
    int rowBlk = blockIdx.x * 128;
    int colBlk = blockIdx.y * 64;
    int tx = t & 15, ty = t >> 4;
    int r0 = ty << 3;                // 0..120
    int c0 = tx << 2;                // 0..60

    int lr0 = t >> 2;                // A row for chunk 0 (0..63)
    int lkq = t & 3;                 // k-quad 0..3
    int lc  = t >> 2;                // B col (0..63)

    ull acc[4][4];
#pragma unroll
    for (int jp = 0; jp < 4; jp++)
#pragma unroll
        for (int l = 0; l < 4; l++) acc[jp][l] = 0ull;

    float4 ra[2], rb;
    {
        int row0 = rowBlk + lr0;
        int row1 = rowBlk + lr0 + 64;
        ra[0] = (row0 < Nn) ? *(const float4*)&src[row0 * 128 + lkq * 4]
                            : make_float4(0.f, 0.f, 0.f, 0.f);
        ra[1] = (row1 < Nn) ? *(const float4*)&src[row1 * 128 + lkq * 4]
                            : make_float4(0.f, 0.f, 0.f, 0.f);
        rb = *(const float4*)&W[(colBlk + lc) * 128 + lkq * 4];
    }
    {
        int kbase = lkq * 4;
        ftT[0][kbase + 0][lr0] = ra[0].x;  ftT[0][kbase + 1][lr0] = ra[0].y;
        ftT[0][kbase + 2][lr0] = ra[0].z;  ftT[0][kbase + 3][lr0] = ra[0].w;
        ftT[0][kbase + 0][lr0 + 64] = ra[1].x;  ftT[0][kbase + 1][lr0 + 64] = ra[1].y;
        ftT[0][kbase + 2][lr0 + 64] = ra[1].z;  ftT[0][kbase + 3][lr0 + 64] = ra[1].w;
        wtT[0][kbase + 0][lc] = rb.x;  wtT[0][kbase + 1][lc] = rb.y;
        wtT[0][kbase + 2][lc] = rb.z;  wtT[0][kbase + 3][lc] = rb.w;
    }
    __syncthreads();

#pragma unroll
    for (int tile = 0; tile < 8; tile++) {
        int cur = tile & 1;
        if (tile < 7) {
            int kb = (tile + 1) * 16;
            int row0 = rowBlk + lr0;
            int row1 = rowBlk + lr0 + 64;
            ra[0] = (row0 < Nn) ? *(const float4*)&src[row0 * 128 + kb + lkq * 4]
                                : make_float4(0.f, 0.f, 0.f, 0.f);
            ra[1] = (row1 < Nn) ? *(const float4*)&src[row1 * 128 + kb + lkq * 4]
                                : make_float4(0.f, 0.f, 0.f, 0.f);
            rb = *(const float4*)&W[(colBlk + lc) * 128 + kb + lkq * 4];
        }
#pragma unroll
        for (int k = 0; k < 16; k++) {
            ulonglong2 a0 = *(const ulonglong2*)&ftT[cur][k][r0];
            ulonglong2 a1 = *(const ulonglong2*)&ftT[cur][k][r0 + 4];
            float4 b = *(const float4*)&wtT[cur][k][c0];
            ull ap[4] = {a0.x, a0.y, a1.x, a1.y};
            ull bp[4];
            PACK2(bp[0], b.x, b.x);
            PACK2(bp[1], b.y, b.y);
            PACK2(bp[2], b.z, b.z);
            PACK2(bp[3], b.w, b.w);
#pragma unroll
            for (int jp = 0; jp < 4; jp++) {
                FMA2(acc[jp][0], ap[jp], bp[0]);
                FMA2(acc[jp][1], ap[jp], bp[1]);
                FMA2(acc[jp][2], ap[jp], bp[2]);
                FMA2(acc[jp][3], ap[jp], bp[3]);
            }
        }
        if (tile < 7) {
            int nxt = cur ^ 1;
            int kbase = lkq * 4;
            ftT[nxt][kbase + 0][lr0] = ra[0].x;  ftT[nxt][kbase + 1][lr0] = ra[0].y;
            ftT[nxt][kbase + 2][lr0] = ra[0].z;  ftT[nxt][kbase + 3][lr0] = ra[0].w;
            ftT[nxt][kbase + 0][lr0 + 64] = ra[1].x;  ftT[nxt][kbase + 1][lr0 + 64] = ra[1].y;
            ftT[nxt][kbase + 2][lr0 + 64] = ra[1].z;  ftT[nxt][kbase + 3][lr0 + 64] = ra[1].w;
            wtT[nxt][kbase + 0][lc] = rb.x;  wtT[nxt][kbase + 1][lc] = rb.y;
            wtT[nxt][kbase + 2][lc] = rb.z;  wtT[nxt][kbase + 3][lc] = rb.w;
            __syncthreads();
        }
    }

    float rv[8][4];
#pragma unroll
    for (int jp = 0; jp < 4; jp++)
#pragma unroll
        for (int l = 0; l < 4; l++)
            UNPACK2(rv[2 * jp][l], rv[2 * jp + 1][l], acc[jp][l]);

    float4 sv = *(const float4*)&AS[colBlk + c0];
    float4 dv = *(const float4*)&AD[colBlk + c0];
    int head = (blockIdx.y << 1) + (tx >> 3);

#pragma unroll
    for (int j = 0; j < 8; j++) {
        int row = rowBlk + r0 + j;
        float ps = rv[j][0] * sv.x + rv[j][1] * sv.y + rv[j][2] * sv.z + rv[j][3] * sv.w;
        float pd = rv[j][0] * dv.x + rv[j][1] * dv.y + rv[j][2] * dv.z + rv[j][3] * dv.w;
        ps += __shfl_xor_sync(0xffffffffu, ps, 1);
        pd += __shfl_xor_sync(0xffffffffu, pd, 1);
        ps += __shfl_xor_sync(0xffffffffu, ps, 2);
        pd += __shfl_xor_sync(0xffffffffu, pd, 2);
        ps += __shfl_xor_sync(0xffffffffu, ps, 4);
        pd += __shfl_xor_sync(0xffffffffu, pd, 4);
        if (row < Nn) {
            // store bf16x2 pairs (h is consumed only by k_agg's weighted sum)
            __nv_bfloat162 p0 = __floats2bfloat162_rn(rv[j][0], rv[j][1]);
            __nv_bfloat162 p1 = __floats2bfloat162_rn(rv[j][2], rv[j][3]);
            uint2 packed;
            packed.x = *reinterpret_cast<unsigned*>(&p0);
            packed.y = *reinterpret_cast<unsigned*>(&p1);
            *(uint2*)&g_hb[row * 128 + colBlk + c0] = packed;
            if ((tx & 7) == 0) {
                g_asrc[row * 4 + head] = ps;
                g_adst[row * 4 + head] = pd;
            }
        }
    }
}

__device__ __forceinline__ float lrelu(float x) { return x > 0.f ? x : NEG * x; }

__device__ __forceinline__ void bf4_to_f4(uint2 raw, float& x, float& y, float& z, float& w) {
    __nv_bfloat162 b0 = *reinterpret_cast<__nv_bfloat162*>(&raw.x);
    __nv_bfloat162 b1 = *reinterpret_cast<__nv_bfloat162*>(&raw.y);
    float2 f0 = __bfloat1622float2(b0);
    float2 f1 = __bfloat1622float2(b1);
    x = f0.x; y = f0.y; z = f1.x; w = f1.y;
}

// ---------------- per-dst-node softmax + aggregation, single pass ----------------
// POOL: final layer — skip g_feat store, atomically accumulate into mean-pool sums.
template<bool POOL>
__global__ __launch_bounds__(256) void k_agg(const float* __restrict__ bias,
                                             const int* __restrict__ batch) {
    int n = (blockIdx.x * 256 + threadIdx.x) >> 5;
    int lane = threadIdx.x & 31;
    if (n >= Nn) return;
    int start = g_rowptr[n], end = g_rowptr[n + 1];
    int head = lane >> 3;
    int ch = lane << 2;
    float adh = g_adst[n * 4 + head];

    float4 acc = make_float4(0.f, 0.f, 0.f, 0.f);
    float den = 0.f;
    int e = start;
    for (; e + 3 < end; e += 4) {
        int s0 = g_col[e], s1 = g_col[e + 1], s2 = g_col[e + 2], s3 = g_col[e + 3];
        float a0 = g_asrc[(s0 << 2) + head];
        float a1 = g_asrc[(s1 << 2) + head];
        float a2 = g_asrc[(s2 << 2) + head];
        float a3 = g_asrc[(s3 << 2) + head];
        uint2 r0 = *(const uint2*)(g_hb + s0 * 128 + ch);
        uint2 r1 = *(const uint2*)(g_hb + s1 * 128 + ch);
        uint2 r2 = *(const uint2*)(g_hb + s2 * 128 + ch);
        uint2 r3 = *(const uint2*)(g_hb + s3 * 128 + ch);
        float w0 = __expf(lrelu(a0 + adh));
        float w1 = __expf(lrelu(a1 + adh));
        float w2 = __expf(lrelu(a2 + adh));
        float w3 = __expf(lrelu(a3 + adh));
        float h0x, h0y, h0z, h0w, h1x, h1y, h1z, h1w;
        float h2x, h2y, h2z, h2w, h3x, h3y, h3z, h3w;
        bf4_to_f4(r0, h0x, h0y, h0z, h0w);
        bf4_to_f4(r1, h1x, h1y, h1z, h1w);
        bf4_to_f4(r2, h2x, h2y, h2z, h2w);
        bf4_to_f4(r3, h3x, h3y, h3z, h3w);
        den += (w0 + w1) + (w2 + w3);
        acc.x += (w0 * h0x + w1 * h1x) + (w2 * h2x + w3 * h3x);
        acc.y += (w0 * h0y + w1 * h1y) + (w2 * h2y + w3 * h3y);
        acc.z += (w0 * h0z + w1 * h1z) + (w2 * h2z + w3 * h3z);
        acc.w += (w0 * h0w + w1 * h1w) + (w2 * h2w + w3 * h3w);
    }
    for (; e < end; e++) {
        int s0 = g_col[e];
        float a0 = g_asrc[(s0 << 2) + head] + adh;
        uint2 r0 = *(const uint2*)(g_hb + s0 * 128 + ch);
        float w0 = __expf(lrelu(a0));
        float h0x, h0y, h0z, h0w;
        bf4_to_f4(r0, h0x, h0y, h0z, h0w);
        den += w0;
        acc.x += w0 * h0x;
        acc.y += w0 * h0y;
        acc.z += w0 * h0z;
        acc.w += w0 * h0w;
    }
    float inv = 1.f / (den + EPSf);
    float4 b4 = *(const float4*)(bias + ch);
    float vx = acc.x * inv + b4.x;
    float vy = acc.y * inv + b4.y;
    float vz = acc.z * inv + b4.z;
    float vw = acc.w * inv + b4.w;
    // ELU
    vx = vx > 0.f ? vx : expm1f(vx);
    vy = vy > 0.f ? vy : expm1f(vy);
    vz = vz > 0.f ? vz : expm1f(vz);
    vw = vw > 0.f ? vw : expm1f(vw);
    if (POOL) {
        int g = batch[n];
        float* sp = &g_sums[g * 128 + ch];
        atomicAdd(sp + 0, vx);
        atomicAdd(sp + 1, vy);
        atomicAdd(sp + 2, vz);
        atomicAdd(sp + 3, vw);
        if (lane == 0) atomicAdd(&g_cnt[g], 1.f);
    } else {
        *(float4*)&g_feat[n * 128 + ch] = make_float4(vx, vy, vz, vw);
    }
}

// ---------------- final FC: out[G,100] = (sums/cnt) @ fcW^T + fcb ----------------
__global__ void k_fc(const float* __restrict__ fcW,
                     const float* __restrict__ fcb,
                     float* __restrict__ out) {
    int i = blockIdx.x * 256 + threadIdx.x;
    if (i >= Gg * OUTC) return;
    int g = i / OUTC, o = i - g * OUTC;
    float inv = 1.f / fmaxf(g_cnt[g], 1.f);
    const float* sr = &g_sums[g * 128];
    const float* wr = &fcW[o * 128];
    float s = 0.f;
#pragma unroll
    for (int c = 0; c < 128; c++) s = fmaf(sr[c], wr[c], s);
    out[i] = s * inv + fcb[o];
}

extern "C" void kernel_launch(void* const* d_in, const int* in_sizes, int n_in,
                              void* d_out, int out_size) {
    const float* x     = (const float*)d_in[0];
    const int*   ei    = (const int*)d_in[1];    // int64 in reference -> staged int32
    const int*   batch = (const int*)d_in[2];
    const float* W1 = (const float*)d_in[3];
    const float* as1 = (const float*)d_in[4];
    const float* ad1 = (const float*)d_in[5];
    const float* b1 = (const float*)d_in[6];
    const float* W2 = (const float*)d_in[7];
    const float* as2 = (const float*)d_in[8];
    const float* ad2 = (const float*)d_in[9];
    const float* b2 = (const float*)d_in[10];
    const float* W3 = (const float*)d_in[11];
    const float* as3 = (const float*)d_in[12];
    const float* ad3 = (const float*)d_in[13];
    const float* b3 = (const float*)d_in[14];
    const float* fcW = (const float*)d_in[15];
    const float* fcb = (const float*)d_in[16];
    float* out = (float*)d_out;

    // CSR build (once per call) + pool accumulator zeroing — serial (overlap
    // with GEMM1 measured WORSE in R8: both throughput-bound).
    k_init<<<256, 256>>>();
    k_hist<<<(Ee / 4 + 255) / 256, 256>>>(ei);
    k_scan<<<1, 1024>>>();
    k_scatter<<<((Ee + Nn) / 4 + 255) / 256, 256>>>(ei);

    dim3 gg((Nn + 127) / 128, 2);
    int aggBlocks = (Nn + 7) / 8;

    // layer 1
    k_gemm<false><<<gg, 256>>>(x, W1, as1, ad1);
    k_agg<false><<<aggBlocks, 256>>>(b1, batch);
    // layer 2
    k_gemm<true><<<gg, 256>>>(nullptr, W2, as2, ad2);
    k_agg<false><<<aggBlocks, 256>>>(b2, batch);
    // layer 3 (pool fused into aggregation epilogue)
    k_gemm<true><<<gg, 256>>>(nullptr, W3, as3, ad3);
    k_agg<true><<<aggBlocks, 256>>>(b3, batch);

    // fc
    k_fc<<<(Gg * OUTC + 255) / 256, 256>>>(fcW, fcb, out);
}

// round 11
// speedup vs baseline: 1.0002x; 1.0002x over previous
#include <cuda_runtime.h>
#include <math.h>

#define Nn   50000
#define Ee   800000
#define ENb  (Ee + Nn)
#define Cc   128
#define Hh   4
#define Gg   512
#define OUTC 100
#define NEG  0.2f
#define EPSf 1e-16f

typedef unsigned long long ull;

#define PACK2(out, lo, hi) \
    asm("mov.b64 %0, {%1, %2};" : "=l"(out) : "r"(__float_as_uint(lo)), "r"(__float_as_uint(hi)))
#define UNPACK2(lo, hi, in) \
    do { unsigned _ul, _uh; \
         asm("mov.b64 {%0, %1}, %2;" : "=r"(_ul), "=r"(_uh) : "l"(in)); \
         lo = __uint_as_float(_ul); hi = __uint_as_float(_uh); } while (0)
#define FMA2(d, a, b) \
    asm("fma.rn.f32x2 %0, %1, %2, %0;" : "+l"(d) : "l"(a), "l"(b))

// ---- scratch (device globals: no allocations allowed) ----
__device__ __align__(16) float g_feat[Nn * Cc];   // layer output / next layer input
__device__ __align__(16) float g_h[Nn * Cc];      // transformed features (gather source)
__device__ __align__(16) float g_asrc[Nn * Hh];
__device__ __align__(16) float g_adst[Nn * Hh];
__device__ int   g_rowptr[Nn + 1];
__device__ int   g_cursor[Nn];
__device__ int   g_col[ENb];
__device__ __align__(16) float g_sums[Gg * Cc];
__device__ float g_cnt[Gg];

// ---------------- init: deg=1 (self loop), zero pool accumulators ----------------
__global__ void k_init() {
    int i = blockIdx.x * 256 + threadIdx.x;
    if (i < Gg * Cc) g_sums[i] = 0.f;
    if (i < Gg)      g_cnt[i]  = 0.f;
    if (i < Nn)      g_cursor[i] = 1;   // self loop counted
}

// ---------------- histogram over dst, 4 edges/thread ----------------
__global__ void k_hist(const int* __restrict__ ei) {
    int idx = blockIdx.x * 256 + threadIdx.x;
    if (idx >= Ee / 4) return;
    int4 d = *(const int4*)&ei[Ee + idx * 4];
    atomicAdd(&g_cursor[d.x], 1);
    atomicAdd(&g_cursor[d.y], 1);
    atomicAdd(&g_cursor[d.z], 1);
    atomicAdd(&g_cursor[d.w], 1);
}

// ---------------- single-block exclusive scan (N=50000) ----------------
__global__ void k_scan() {
    __shared__ int s[1024];
    int t = threadIdx.x;
    const int PER = (Nn + 1023) / 1024;   // 49
    int base = t * PER;
    int sum = 0;
    for (int i = 0; i < PER; i++) {
        int idx = base + i;
        if (idx < Nn) sum += g_cursor[idx];
    }
    s[t] = sum;
    __syncthreads();
    for (int o = 1; o < 1024; o <<= 1) {
        int u = (t >= o) ? s[t - o] : 0;
        __syncthreads();
        s[t] += u;
        __syncthreads();
    }
    int off = s[t] - sum;                 // exclusive prefix
    for (int i = 0; i < PER; i++) {
        int idx = base + i;
        if (idx < Nn) {
            int d = g_cursor[idx];
            g_rowptr[idx] = off;
            g_cursor[idx] = off;          // scatter cursor
            off += d;
        }
    }
    if (t == 1023) g_rowptr[Nn] = s[1023];
}

// ---------------- scatter edges + self loops into CSR, 4/thread ----------------
__global__ void k_scatter(const int* __restrict__ ei) {
    int idx = blockIdx.x * 256 + threadIdx.x;
    const int EQ = Ee / 4;                 // 200000
    const int NQ = Nn / 4;                 // 12500
    if (idx < EQ) {
        int4 d = *(const int4*)&ei[Ee + idx * 4];
        int4 s = *(const int4*)&ei[idx * 4];
        int p0 = atomicAdd(&g_cursor[d.x], 1);
        int p1 = atomicAdd(&g_cursor[d.y], 1);
        int p2 = atomicAdd(&g_cursor[d.z], 1);
        int p3 = atomicAdd(&g_cursor[d.w], 1);
        g_col[p0] = s.x;
        g_col[p1] = s.y;
        g_col[p2] = s.z;
        g_col[p3] = s.w;
    } else if (idx < EQ + NQ) {
        int n = (idx - EQ) * 4;
        int p0 = atomicAdd(&g_cursor[n + 0], 1);
        int p1 = atomicAdd(&g_cursor[n + 1], 1);
        int p2 = atomicAdd(&g_cursor[n + 2], 1);
        int p3 = atomicAdd(&g_cursor[n + 3], 1);
        g_col[p0] = n + 0;
        g_col[p1] = n + 1;
        g_col[p2] = n + 2;
        g_col[p3] = n + 3;
    }
}

// ---------------- fused GEMM (f32x2, double-buffered) + attention logits ----------------
// g_h[N,128] = X[N,128] @ W[128,128]^T, plus per-head att dots (fp32).
// BM=128, BN=64, BK=16, 256 threads, 8x4 per thread, f32x2 row-pair accumulators.
template<bool FROM_GLOBAL>
__global__ __launch_bounds__(256) void k_gemm(const float* __restrict__ X,
                                              const float* __restrict__ W,
                                              const float* __restrict__ AS,
                                              const float* __restrict__ AD) {
    __shared__ __align__(16) float ftT[2][16][132];   // [buf][k][row]
    __shared__ __align__(16) float wtT[2][16][68];    // [buf][k][col]
    const float* __restrict__ src = FROM_GLOBAL ? (const float*)g_feat : X;
    int t = threadIdx.x;
    int rowBlk = blockIdx.x * 128;
    int colBlk = blockIdx.y * 64;
    int tx = t & 15, ty = t >> 4;
    int r0 = ty << 3;                // 0..120
    int c0 = tx << 2;                // 0..60

    int lr0 = t >> 2;                // A row for chunk 0 (0..63)
    int lkq = t & 3;                 // k-quad 0..3
    int lc  = t >> 2;                // B col (0..63)

    ull acc[4][4];
#pragma unroll
    for (int jp = 0; jp < 4; jp++)
#pragma unroll
        for (int l = 0; l < 4; l++) acc[jp][l] = 0ull;

    float4 ra[2], rb;
    {
        int row0 = rowBlk + lr0;
        int row1 = rowBlk + lr0 + 64;
        ra[0] = (row0 < Nn) ? *(const float4*)&src[row0 * 128 + lkq * 4]
                            : make_float4(0.f, 0.f, 0.f, 0.f);
        ra[1] = (row1 < Nn) ? *(const float4*)&src[row1 * 128 + lkq * 4]
                            : make_float4(0.f, 0.f, 0.f, 0.f);
        rb = *(const float4*)&W[(colBlk + lc) * 128 + lkq * 4];
    }
    {
        int kbase = lkq * 4;
        ftT[0][kbase + 0][lr0] = ra[0].x;  ftT[0][kbase + 1][lr0] = ra[0].y;
        ftT[0][kbase + 2][lr0] = ra[0].z;  ftT[0][kbase + 3][lr0] = ra[0].w;
        ftT[0][kbase + 0][lr0 + 64] = ra[1].x;  ftT[0][kbase + 1][lr0 + 64] = ra[1].y;
        ftT[0][kbase + 2][lr0 + 64] = ra[1].z;  ftT[0][kbase + 3][lr0 + 64] = ra[1].w;
        wtT[0][kbase + 0][lc] = rb.x;  wtT[0][kbase + 1][lc] = rb.y;
        wtT[0][kbase + 2][lc] = rb.z;  wtT[0][kbase + 3][lc] = rb.w;
    }
    __syncthreads();

#pragma unroll
    for (int tile = 0; tile < 8; tile++) {
        int cur = tile & 1;
        if (tile < 7) {
            int kb = (tile + 1) * 16;
            int row0 = rowBlk + lr0;
            int row1 = rowBlk + lr0 + 64;
            ra[0] = (row0 < Nn) ? *(const float4*)&src[row0 * 128 + kb + lkq * 4]
                                : make_float4(0.f, 0.f, 0.f, 0.f);
            ra[1] = (row1 < Nn) ? *(const float4*)&src[row1 * 128 + kb + lkq * 4]
                                : make_float4(0.f, 0.f, 0.f, 0.f);
            rb = *(const float4*)&W[(colBlk + lc) * 128 + kb + lkq * 4];
        }
#pragma unroll
        for (int k = 0; k < 16; k++) {
            ulonglong2 a0 = *(const ulonglong2*)&ftT[cur][k][r0];
            ulonglong2 a1 = *(const ulonglong2*)&ftT[cur][k][r0 + 4];
            float4 b = *(const float4*)&wtT[cur][k][c0];
            ull ap[4] = {a0.x, a0.y, a1.x, a1.y};
            ull bp[4];
            PACK2(bp[0], b.x, b.x);
            PACK2(bp[1], b.y, b.y);
            PACK2(bp[2], b.z, b.z);
            PACK2(bp[3], b.w, b.w);
#pragma unroll
            for (int jp = 0; jp < 4; jp++) {
                FMA2(acc[jp][0], ap[jp], bp[0]);
                FMA2(acc[jp][1], ap[jp], bp[1]);
                FMA2(acc[jp][2], ap[jp], bp[2]);
                FMA2(acc[jp][3], ap[jp], bp[3]);
            }
        }
        if (tile < 7) {
            int nxt = cur ^ 1;
            int kbase = lkq * 4;
            ftT[nxt][kbase + 0][lr0] = ra[0].x;  ftT[nxt][kbase + 1][lr0] = ra[0].y;
            ftT[nxt][kbase + 2][lr0] = ra[0].z;  ftT[nxt][kbase + 3][lr0] = ra[0].w;
            ftT[nxt][kbase + 0][lr0 + 64] = ra[1].x;  ftT[nxt][kbase + 1][lr0 + 64] = ra[1].y;
            ftT[nxt][kbase + 2][lr0 + 64] = ra[1].z;  ftT[nxt][kbase + 3][lr0 + 64] = ra[1].w;
            wtT[nxt][kbase + 0][lc] = rb.x;  wtT[nxt][kbase + 1][lc] = rb.y;
            wtT[nxt][kbase + 2][lc] = rb.z;  wtT[nxt][kbase + 3][lc] = rb.w;
            __syncthreads();
        }
    }

    float rv[8][4];
#pragma unroll
    for (int jp = 0; jp < 4; jp++)
#pragma unroll
        for (int l = 0; l < 4; l++)
            UNPACK2(rv[2 * jp][l], rv[2 * jp + 1][l], acc[jp][l]);

    float4 sv = *(const float4*)&AS[colBlk + c0];
    float4 dv = *(const float4*)&AD[colBlk + c0];
    int head = (blockIdx.y << 1) + (tx >> 3);

#pragma unroll
    for (int j = 0; j < 8; j++) {
        int row = rowBlk + r0 + j;
        float ps = rv[j][0] * sv.x + rv[j][1] * sv.y + rv[j][2] * sv.z + rv[j][3] * sv.w;
        float pd = rv[j][0] * dv.x + rv[j][1] * dv.y + rv[j][2] * dv.z + rv[j][3] * dv.w;
        ps += __shfl_xor_sync(0xffffffffu, ps, 1);
        pd += __shfl_xor_sync(0xffffffffu, pd, 1);
        ps += __shfl_xor_sync(0xffffffffu, ps, 2);
        pd += __shfl_xor_sync(0xffffffffu, pd, 2);
        ps += __shfl_xor_sync(0xffffffffu, ps, 4);
        pd += __shfl_xor_sync(0xffffffffu, pd, 4);
        if (row < Nn) {
            *(float4*)&g_h[row * 128 + colBlk + c0] =
                make_float4(rv[j][0], rv[j][1], rv[j][2], rv[j][3]);
            if ((tx & 7) == 0) {
                g_asrc[row * 4 + head] = ps;
                g_adst[row * 4 + head] = pd;
            }
        }
    }
}

__device__ __forceinline__ float lrelu(float x) { return x > 0.f ? x : NEG * x; }

// ---------------- per-dst-node softmax + aggregation, single pass ----------------
// Col indices for iteration i+1 are prefetched while iteration i's gathers are
// in flight — hides one of the two serialized L2 hops per iteration.
// POOL: final layer — skip g_feat store, accumulate into mean-pool sums.
template<bool POOL>
__global__ __launch_bounds__(256) void k_agg(const float* __restrict__ bias,
                                             const int* __restrict__ batch) {
    int n = (blockIdx.x * 256 + threadIdx.x) >> 5;
    int lane = threadIdx.x & 31;
    if (n >= Nn) return;
    int start = g_rowptr[n], end = g_rowptr[n + 1];
    int head = lane >> 3;
    int ch = lane << 2;
    float adh = g_adst[n * 4 + head];

    float4 acc = make_float4(0.f, 0.f, 0.f, 0.f);
    float den = 0.f;
    int e = start;
    int s0, s1, s2, s3;
    if (e + 3 < end) {           // prologue: fetch first col group
        s0 = g_col[e]; s1 = g_col[e + 1]; s2 = g_col[e + 2]; s3 = g_col[e + 3];
    }
    for (; e + 3 < end; e += 4) {
        // prefetch next iteration's cols (overlaps with this iteration's gathers)
        int n0, n1, n2, n3;
        bool more = (e + 7 < end);
        if (more) {
            n0 = g_col[e + 4]; n1 = g_col[e + 5]; n2 = g_col[e + 6]; n3 = g_col[e + 7];
        }
        float a0 = g_asrc[(s0 << 2) + head];
        float a1 = g_asrc[(s1 << 2) + head];
        float a2 = g_asrc[(s2 << 2) + head];
        float a3 = g_asrc[(s3 << 2) + head];
        float4 h0 = *(const float4*)(g_h + s0 * 128 + ch);
        float4 h1 = *(const float4*)(g_h + s1 * 128 + ch);
        float4 h2 = *(const float4*)(g_h + s2 * 128 + ch);
        float4 h3 = *(const float4*)(g_h + s3 * 128 + ch);
        float w0 = __expf(lrelu(a0 + adh));
        float w1 = __expf(lrelu(a1 + adh));
        float w2 = __expf(lrelu(a2 + adh));
        float w3 = __expf(lrelu(a3 + adh));
        den += (w0 + w1) + (w2 + w3);
        acc.x += (w0 * h0.x + w1 * h1.x) + (w2 * h2.x + w3 * h3.x);
        acc.y += (w0 * h0.y + w1 * h1.y) + (w2 * h2.y + w3 * h3.y);
        acc.z += (w0 * h0.z + w1 * h1.z) + (w2 * h2.z + w3 * h3.z);
        acc.w += (w0 * h0.w + w1 * h1.w) + (w2 * h2.w + w3 * h3.w);
        if (more) { s0 = n0; s1 = n1; s2 = n2; s3 = n3; }
    }
    for (; e < end; e++) {
        int s = g_col[e];
        float a0 = g_asrc[(s << 2) + head] + adh;
        float4 h0 = *(const float4*)(g_h + s * 128 + ch);
        float w0 = __expf(lrelu(a0));
        den += w0;
        acc.x += w0 * h0.x;
        acc.y += w0 * h0.y;
        acc.z += w0 * h0.z;
        acc.w += w0 * h0.w;
    }
    float inv = 1.f / (den + EPSf);
    float4 b4 = *(const float4*)(bias + ch);
    float vx = acc.x * inv + b4.x;
    float vy = acc.y * inv + b4.y;
    float vz = acc.z * inv + b4.z;
    float vw = acc.w * inv + b4.w;
    // ELU
    vx = vx > 0.f ? vx : expm1f(vx);
    vy = vy > 0.f ? vy : expm1f(vy);
    vz = vz > 0.f ? vz : expm1f(vz);
    vw = vw > 0.f ? vw : expm1f(vw);
    if (POOL) {
        int g = batch[n];
        float* sp = &g_sums[g * 128 + ch];
        atomicAdd(sp + 0, vx);
        atomicAdd(sp + 1, vy);
        atomicAdd(sp + 2, vz);
        atomicAdd(sp + 3, vw);
        if (lane == 0) atomicAdd(&g_cnt[g], 1.f);
    } else {
        *(float4*)&g_feat[n * 128 + ch] = make_float4(vx, vy, vz, vw);
    }
}

// ---------------- final FC: out[G,100] = (sums/cnt) @ fcW^T + fcb ----------------
__global__ void k_fc(const float* __restrict__ fcW,
                     const float* __restrict__ fcb,
                     float* __restrict__ out) {
    int i = blockIdx.x * 256 + threadIdx.x;
    if (i >= Gg * OUTC) return;
    int g = i / OUTC, o = i - g * OUTC;
    float inv = 1.f / fmaxf(g_cnt[g], 1.f);
    const float* sr = &g_sums[g * 128];
    const float* wr = &fcW[o * 128];
    float s = 0.f;
#pragma unroll
    for (int c = 0; c < 128; c++) s = fmaf(sr[c], wr[c], s);
    out[i] = s * inv + fcb[o];
}

extern "C" void kernel_launch(void* const* d_in, const int* in_sizes, int n_in,
                              void* d_out, int out_size) {
    const float* x     = (const float*)d_in[0];
    const int*   ei    = (const int*)d_in[1];    // int64 in reference -> staged int32
    const int*   batch = (const int*)d_in[2];
    const float* W1 = (const float*)d_in[3];
    const float* as1 = (const float*)d_in[4];
    const float* ad1 = (const float*)d_in[5];
    const float* b1 = (const float*)d_in[6];
    const float* W2 = (const float*)d_in[7];
    const float* as2 = (const float*)d_in[8];
    const float* ad2 = (const float*)d_in[9];
    const float* b2 = (const float*)d_in[10];
    const float* W3 = (const float*)d_in[11];
    const float* as3 = (const float*)d_in[12];
    const float* ad3 = (const float*)d_in[13];
    const float* b3 = (const float*)d_in[14];
    const float* fcW = (const float*)d_in[15];
    const float* fcb = (const float*)d_in[16];
    float* out = (float*)d_out;

    dim3 gg((Nn + 127) / 128, 2);
    int aggBlocks = (Nn + 7) / 8;

    // CSR build + layer-1 GEMM, serial on one stream. gemm1 is hoisted before
    // k_scatter (it doesn't depend on the CSR) so the profiler's fixed sample
    // index lands on the GEMM instead of k_scatter.
    k_init<<<256, 256>>>();
    k_hist<<<(Ee / 4 + 255) / 256, 256>>>(ei);
    k_scan<<<1, 1024>>>();
    k_gemm<false><<<gg, 256>>>(x, W1, as1, ad1);
    k_scatter<<<((Ee + Nn) / 4 + 255) / 256, 256>>>(ei);

    // layer 1 aggregation
    k_agg<false><<<aggBlocks, 256>>>(b1, batch);
    // layer 2
    k_gemm<true><<<gg, 256>>>(nullptr, W2, as2, ad2);
    k_agg<false><<<aggBlocks, 256>>>(b2, batch);
    // layer 3 (pool fused into aggregation epilogue)
    k_gemm<true><<<gg, 256>>>(nullptr, W3, as3, ad3);
    k_agg<true><<<aggBlocks, 256>>>(b3, batch);

    // fc
    k_fc<<<(Gg * OUTC + 255) / 256, 256>>>(fcW, fcb, out);
}

// round 12
// speedup vs baseline: 1.0252x; 1.0250x over previous
#include <cuda_runtime.h>
#include <math.h>

#define Nn   50000
#define Ee   800000
#define ENb  (Ee + Nn)
#define Cc   128
#define Hh   4
#define Gg   512
#define OUTC 100
#define NEG  0.2f
#define EPSf 1e-16f

typedef unsigned long long ull;

#define PACK2(out, lo, hi) \
    asm("mov.b64 %0, {%1, %2};" : "=l"(out) : "r"(__float_as_uint(lo)), "r"(__float_as_uint(hi)))
#define UNPACK2(lo, hi, in) \
    do { unsigned _ul, _uh; \
         asm("mov.b64 {%0, %1}, %2;" : "=r"(_ul), "=r"(_uh) : "l"(in)); \
         lo = __uint_as_float(_ul); hi = __uint_as_float(_uh); } while (0)
#define FMA2(d, a, b) \
    asm("fma.rn.f32x2 %0, %1, %2, %0;" : "+l"(d) : "l"(a), "l"(b))

// ---- scratch (device globals: no allocations allowed) ----
__device__ __align__(16) float g_feat[Nn * Cc];   // layer output / next layer input
__device__ __align__(16) float g_h[Nn * Cc];      // transformed features (gather source)
__device__ __align__(16) float g_asrc[Nn * Hh];
__device__ __align__(16) float g_adst[Nn * Hh];
__device__ int   g_rowptr[Nn + 1];
__device__ int   g_cursor[Nn];
__device__ int   g_col[ENb];
__device__ __align__(16) float g_sums[Gg * Cc];
__device__ float g_cnt[Gg];

// ---------------- init: deg=1 (self loop), zero pool accumulators ----------------
__global__ void k_init() {
    int i = blockIdx.x * 256 + threadIdx.x;
    if (i < Gg * Cc) g_sums[i] = 0.f;
    if (i < Gg)      g_cnt[i]  = 0.f;
    if (i < Nn)      g_cursor[i] = 1;   // self loop counted
}

// ---------------- histogram over dst, 4 edges/thread ----------------
__global__ void k_hist(const int* __restrict__ ei) {
    int idx = blockIdx.x * 256 + threadIdx.x;
    if (idx >= Ee / 4) return;
    int4 d = *(const int4*)&ei[Ee + idx * 4];
    atomicAdd(&g_cursor[d.x], 1);
    atomicAdd(&g_cursor[d.y], 1);
    atomicAdd(&g_cursor[d.z], 1);
    atomicAdd(&g_cursor[d.w], 1);
}

// ---------------- single-block exclusive scan (N=50000) ----------------
__global__ void k_scan() {
    __shared__ int s[1024];
    int t = threadIdx.x;
    const int PER = (Nn + 1023) / 1024;   // 49
    int base = t * PER;
    int sum = 0;
    for (int i = 0; i < PER; i++) {
        int idx = base + i;
        if (idx < Nn) sum += g_cursor[idx];
    }
    s[t] = sum;
    __syncthreads();
    for (int o = 1; o < 1024; o <<= 1) {
        int u = (t >= o) ? s[t - o] : 0;
        __syncthreads();
        s[t] += u;
        __syncthreads();
    }
    int off = s[t] - sum;                 // exclusive prefix
    for (int i = 0; i < PER; i++) {
        int idx = base + i;
        if (idx < Nn) {
            int d = g_cursor[idx];
            g_rowptr[idx] = off;
            g_cursor[idx] = off;          // scatter cursor
            off += d;
        }
    }
    if (t == 1023) g_rowptr[Nn] = s[1023];
}

// ---------------- scatter edges + self loops into CSR, 4/thread ----------------
__global__ void k_scatter(const int* __restrict__ ei) {
    int idx = blockIdx.x * 256 + threadIdx.x;
    const int EQ = Ee / 4;                 // 200000
    const int NQ = Nn / 4;                 // 12500
    if (idx < EQ) {
        int4 d = *(const int4*)&ei[Ee + idx * 4];
        int4 s = *(const int4*)&ei[idx * 4];
        int p0 = atomicAdd(&g_cursor[d.x], 1);
        int p1 = atomicAdd(&g_cursor[d.y], 1);
        int p2 = atomicAdd(&g_cursor[d.z], 1);
        int p3 = atomicAdd(&g_cursor[d.w], 1);
        g_col[p0] = s.x;
        g_col[p1] = s.y;
        g_col[p2] = s.z;
        g_col[p3] = s.w;
    } else if (idx < EQ + NQ) {
        int n = (idx - EQ) * 4;
        int p0 = atomicAdd(&g_cursor[n + 0], 1);
        int p1 = atomicAdd(&g_cursor[n + 1], 1);
        int p2 = atomicAdd(&g_cursor[n + 2], 1);
        int p3 = atomicAdd(&g_cursor[n + 3], 1);
        g_col[p0] = n + 0;
        g_col[p1] = n + 1;
        g_col[p2] = n + 2;
        g_col[p3] = n + 3;
    }
}

// ---------------- fused GEMM (f32x2, double-buffered, 8x8) + attention logits ----------------
// g_h[N,128] = X[N,128] @ W[128,128]^T, plus per-head att dots (fp32).
// BM=128, BN=128, BK=16, 256 threads, 8x8 per thread (f32x2 row-pair accs).
// Per k: 64B LDS for 32 FMA2 (2B/FMA2, was 3) — attacks the measured L1=69% ceiling.
template<bool FROM_GLOBAL>
__global__ __launch_bounds__(256, 2) void k_gemm(const float* __restrict__ X,
                                                 const float* __restrict__ W,
                                                 const float* __restrict__ AS,
                                                 const float* __restrict__ AD) {
    __shared__ __align__(16) float ftT[2][16][132];   // [buf][k][row]
    __shared__ __align__(16) float wtT[2][16][132];   // [buf][k][col]
    const float* __restrict__ src = FROM_GLOBAL ? (const float*)g_feat : X;
    int t = threadIdx.x;
    int rowBlk = blockIdx.x * 128;
    int tx = t & 15, ty = t >> 4;
    int r0 = ty << 3;                // 0..120
    int c0 = tx << 3;                // 0..120

    int lr0 = t >> 2;                // A row / W col for chunk 0 (0..63)
    int lkq = t & 3;                 // k-quad 0..3

    ull acc[4][8];                   // [row-pair][col]
#pragma unroll
    for (int jp = 0; jp < 4; jp++)
#pragma unroll
        for (int l = 0; l < 8; l++) acc[jp][l] = 0ull;

    float4 ra[2], rb[2];
    {
        int row0 = rowBlk + lr0;
        int row1 = rowBlk + lr0 + 64;
        ra[0] = (row0 < Nn) ? *(const float4*)&src[row0 * 128 + lkq * 4]
                            : make_float4(0.f, 0.f, 0.f, 0.f);
        ra[1] = (row1 < Nn) ? *(const float4*)&src[row1 * 128 + lkq * 4]
                            : make_float4(0.f, 0.f, 0.f, 0.f);
        rb[0] = *(const float4*)&W[lr0 * 128 + lkq * 4];
        rb[1] = *(const float4*)&W[(lr0 + 64) * 128 + lkq * 4];
    }
    {
        int kbase = lkq * 4;
#pragma unroll
        for (int i = 0; i < 4; i++) {
            ftT[0][kbase + i][lr0]      = ((const float*)&ra[0])[i];
            ftT[0][kbase + i][lr0 + 64] = ((const float*)&ra[1])[i];
            wtT[0][kbase + i][lr0]      = ((const float*)&rb[0])[i];
            wtT[0][kbase + i][lr0 + 64] = ((const float*)&rb[1])[i];
        }
    }
    __syncthreads();

#pragma unroll
    for (int tile = 0; tile < 8; tile++) {
        int cur = tile & 1;
        if (tile < 7) {
            int kb = (tile + 1) * 16;
            int row0 = rowBlk + lr0;
            int row1 = rowBlk + lr0 + 64;
            ra[0] = (row0 < Nn) ? *(const float4*)&src[row0 * 128 + kb + lkq * 4]
                                : make_float4(0.f, 0.f, 0.f, 0.f);
            ra[1] = (row1 < Nn) ? *(const float4*)&src[row1 * 128 + kb + lkq * 4]
                                : make_float4(0.f, 0.f, 0.f, 0.f);
            rb[0] = *(const float4*)&W[lr0 * 128 + kb + lkq * 4];
            rb[1] = *(const float4*)&W[(lr0 + 64) * 128 + kb + lkq * 4];
        }
#pragma unroll
        for (int k = 0; k < 16; k++) {
            ulonglong2 a0 = *(const ulonglong2*)&ftT[cur][k][r0];      // rows r0..r0+3 (broadcast per half-warp)
            ulonglong2 a1 = *(const ulonglong2*)&ftT[cur][k][r0 + 4];
            float4 b0 = *(const float4*)&wtT[cur][k][c0];
            float4 b1 = *(const float4*)&wtT[cur][k][c0 + 4];
            ull ap[4] = {a0.x, a0.y, a1.x, a1.y};
            ull bp[8];
            PACK2(bp[0], b0.x, b0.x);
            PACK2(bp[1], b0.y, b0.y);
            PACK2(bp[2], b0.z, b0.z);
            PACK2(bp[3], b0.w, b0.w);
            PACK2(bp[4], b1.x, b1.x);
            PACK2(bp[5], b1.y, b1.y);
            PACK2(bp[6], b1.z, b1.z);
            PACK2(bp[7], b1.w, b1.w);
#pragma unroll
            for (int jp = 0; jp < 4; jp++)
#pragma unroll
                for (int l = 0; l < 8; l++)
                    FMA2(acc[jp][l], ap[jp], bp[l]);
        }
        if (tile < 7) {
            int nxt = cur ^ 1;
            int kbase = lkq * 4;
#pragma unroll
            for (int i = 0; i < 4; i++) {
                ftT[nxt][kbase + i][lr0]      = ((const float*)&ra[0])[i];
                ftT[nxt][kbase + i][lr0 + 64] = ((const float*)&ra[1])[i];
                wtT[nxt][kbase + i][lr0]      = ((const float*)&rb[0])[i];
                wtT[nxt][kbase + i][lr0 + 64] = ((const float*)&rb[1])[i];
            }
            __syncthreads();
        }
    }

    // unpack accumulators into per-row values
    float rv[8][8];
#pragma unroll
    for (int jp = 0; jp < 4; jp++)
#pragma unroll
        for (int l = 0; l < 8; l++)
            UNPACK2(rv[2 * jp][l], rv[2 * jp + 1][l], acc[jp][l]);

    // att vectors for this thread's 8 columns (c0 8-aligned within a 32-wide head)
    float4 s0v = *(const float4*)&AS[c0];
    float4 s1v = *(const float4*)&AS[c0 + 4];
    float4 d0v = *(const float4*)&AD[c0];
    float4 d1v = *(const float4*)&AD[c0 + 4];
    float sv[8] = {s0v.x, s0v.y, s0v.z, s0v.w, s1v.x, s1v.y, s1v.z, s1v.w};
    float dv[8] = {d0v.x, d0v.y, d0v.z, d0v.w, d1v.x, d1v.y, d1v.z, d1v.w};
    int head = tx >> 2;

#pragma unroll
    for (int j = 0; j < 8; j++) {
        int row = rowBlk + r0 + j;
        float ps = 0.f, pd = 0.f;
#pragma unroll
        for (int l = 0; l < 8; l++) {
            ps = fmaf(rv[j][l], sv[l], ps);
            pd = fmaf(rv[j][l], dv[l], pd);
        }
        // reduce over the 4 threads (tx bits 0,1) covering one 32-col head
        ps += __shfl_xor_sync(0xffffffffu, ps, 1);
        pd += __shfl_xor_sync(0xffffffffu, pd, 1);
        ps += __shfl_xor_sync(0xffffffffu, ps, 2);
        pd += __shfl_xor_sync(0xffffffffu, pd, 2);
        if (row < Nn) {
            *(float4*)&g_h[row * 128 + c0] =
                make_float4(rv[j][0], rv[j][1], rv[j][2], rv[j][3]);
            *(float4*)&g_h[row * 128 + c0 + 4] =
                make_float4(rv[j][4], rv[j][5], rv[j][6], rv[j][7]);
            if ((tx & 3) == 0) {
                g_asrc[row * 4 + head] = ps;
                g_adst[row * 4 + head] = pd;
            }
        }
    }
}

__device__ __forceinline__ float lrelu(float x) { return x > 0.f ? x : NEG * x; }

// ---------------- per-dst-node softmax + aggregation, single pass, MLP=8 ----------------
// POOL: final layer — skip g_feat store, accumulate into mean-pool sums.
template<bool POOL>
__global__ __launch_bounds__(256) void k_agg(const float* __restrict__ bias,
                                             const int* __restrict__ batch) {
    int n = (blockIdx.x * 256 + threadIdx.x) >> 5;
    int lane = threadIdx.x & 31;
    if (n >= Nn) return;
    int start = g_rowptr[n], end = g_rowptr[n + 1];
    int head = lane >> 3;
    int ch = lane << 2;
    float adh = g_adst[n * 4 + head];

    float4 acc = make_float4(0.f, 0.f, 0.f, 0.f);
    float den = 0.f;
    int e = start;
    for (; e + 7 < end; e += 8) {
        int ss[8];
#pragma unroll
        for (int q = 0; q < 8; q++) ss[q] = g_col[e + q];
        float aa[8];
        float4 hh[8];
#pragma unroll
        for (int q = 0; q < 8; q++) aa[q] = g_asrc[(ss[q] << 2) + head];
#pragma unroll
        for (int q = 0; q < 8; q++) hh[q] = *(const float4*)(g_h + ss[q] * 128 + ch);
#pragma unroll
        for (int q = 0; q < 8; q++) {
            float w = __expf(lrelu(aa[q] + adh));
            den += w;
            acc.x += w * hh[q].x;
            acc.y += w * hh[q].y;
            acc.z += w * hh[q].z;
            acc.w += w * hh[q].w;
        }
    }
    for (; e + 3 < end; e += 4) {
        int ss[4];
#pragma unroll
        for (int q = 0; q < 4; q++) ss[q] = g_col[e + q];
        float aa[4];
        float4 hh[4];
#pragma unroll
        for (int q = 0; q < 4; q++) aa[q] = g_asrc[(ss[q] << 2) + head];
#pragma unroll
        for (int q = 0; q < 4; q++) hh[q] = *(const float4*)(g_h + ss[q] * 128 + ch);
#pragma unroll
        for (int q = 0; q < 4; q++) {
            float w = __expf(lrelu(aa[q] + adh));
            den += w;
            acc.x += w * hh[q].x;
            acc.y += w * hh[q].y;
            acc.z += w * hh[q].z;
            acc.w += w * hh[q].w;
        }
    }
    for (; e < end; e++) {
        int s = g_col[e];
        float a0 = g_asrc[(s << 2) + head] + adh;
        float4 h0 = *(const float4*)(g_h + s * 128 + ch);
        float w0 = __expf(lrelu(a0));
        den += w0;
        acc.x += w0 * h0.x;
        acc.y += w0 * h0.y;
        acc.z += w0 * h0.z;
        acc.w += w0 * h0.w;
    }
    float inv = 1.f / (den + EPSf);
    float4 b4 = *(const float4*)(bias + ch);
    float vx = acc.x * inv + b4.x;
    float vy = acc.y * inv + b4.y;
    float vz = acc.z * inv + b4.z;
    float vw = acc.w * inv + b4.w;
    // ELU
    vx = vx > 0.f ? vx : expm1f(vx);
    vy = vy > 0.f ? vy : expm1f(vy);
    vz = vz > 0.f ? vz : expm1f(vz);
    vw = vw > 0.f ? vw : expm1f(vw);
    if (POOL) {
        int g = batch[n];
        float* sp = &g_sums[g * 128 + ch];
        atomicAdd(sp + 0, vx);
        atomicAdd(sp + 1, vy);
        atomicAdd(sp + 2, vz);
        atomicAdd(sp + 3, vw);
        if (lane == 0) atomicAdd(&g_cnt[g], 1.f);
    } else {
        *(float4*)&g_feat[n * 128 + ch] = make_float4(vx, vy, vz, vw);
    }
}

// ---------------- final FC: out[G,100] = (sums/cnt) @ fcW^T + fcb ----------------
__global__ void k_fc(const float* __restrict__ fcW,
                     const float* __restrict__ fcb,
                     float* __restrict__ out) {
    int i = blockIdx.x * 256 + threadIdx.x;
    if (i >= Gg * OUTC) return;
    int g = i / OUTC, o = i - g * OUTC;
    float inv = 1.f / fmaxf(g_cnt[g], 1.f);
    const float* sr = &g_sums[g * 128];
    const float* wr = &fcW[o * 128];
    float s = 0.f;
#pragma unroll
    for (int c = 0; c < 128; c++) s = fmaf(sr[c], wr[c], s);
    out[i] = s * inv + fcb[o];
}

extern "C" void kernel_launch(void* const* d_in, const int* in_sizes, int n_in,
                              void* d_out, int out_size) {
    const float* x     = (const float*)d_in[0];
    const int*   ei    = (const int*)d_in[1];    // int64 in reference -> staged int32
    const int*   batch = (const int*)d_in[2];
    const float* W1 = (const float*)d_in[3];
    const float* as1 = (const float*)d_in[4];
    const float* ad1 = (const float*)d_in[5];
    const float* b1 = (const float*)d_in[6];
    const float* W2 = (const float*)d_in[7];
    const float* as2 = (const float*)d_in[8];
    const float* ad2 = (const float*)d_in[9];
    const float* b2 = (const float*)d_in[10];
    const float* W3 = (const float*)d_in[11];
    const float* as3 = (const float*)d_in[12];
    const float* ad3 = (const float*)d_in[13];
    const float* b3 = (const float*)d_in[14];
    const float* fcW = (const float*)d_in[15];
    const float* fcb = (const float*)d_in[16];
    float* out = (float*)d_out;

    int gemmBlocks = (Nn + 127) / 128;   // 391
    int aggBlocks = (Nn + 7) / 8;

    // CSR build + layer-1 GEMM, serial. gemm1 hoisted before k_scatter (it
    // doesn't depend on the CSR) so ncu's sample lands on the GEMM.
    k_init<<<256, 256>>>();
    k_hist<<<(Ee / 4 + 255) / 256, 256>>>(ei);
    k_scan<<<1, 1024>>>();
    k_gemm<false><<<gemmBlocks, 256>>>(x, W1, as1, ad1);
    k_scatter<<<((Ee + Nn) / 4 + 255) / 256, 256>>>(ei);

    // layer 1 aggregation
    k_agg<false><<<aggBlocks, 256>>>(b1, batch);
    // layer 2
    k_gemm<true><<<gemmBlocks, 256>>>(nullptr, W2, as2, ad2);
    k_agg<false><<<aggBlocks, 256>>>(b2, batch);
    // layer 3 (pool fused into aggregation epilogue)
    k_gemm<true><<<gemmBlocks, 256>>>(nullptr, W3, as3, ad3);
    k_agg<true><<<aggBlocks, 256>>>(b3, batch);

    // fc
    k_fc<<<(Gg * OUTC + 255) / 256, 256>>>(fcW, fcb, out);
}